// round 2
// baseline (speedup 1.0000x reference)
#include <cuda_runtime.h>
#include <cstdint>

// Problem shape (fixed by dataset)
#define PP 1024
#define NN 16384
#define TM 128   // row tile
#define TN 64    // k (output-col) tile
#define TJ 16    // reduction tile
#define NKT (PP / TN)   // 16 k-tiles

// Scratch (no cudaMalloc allowed): W scatter target + per-(k-tile) partial sums
__device__ float g_W[PP * PP];               // 4 MB, strictly upper triangular
__device__ float g_ypart[NKT * NN];          // 1 MB partials

// ---------------------------------------------------------------------------
// Kernel 1: scatter packed upper-tri theta into full [P,P] matrix (zeros elsewhere)
// theta index for (j,k>j): t = j*P - j*(j+1)/2 + (k - j - 1)
// ---------------------------------------------------------------------------
__global__ void scatter_theta_kernel(const float* __restrict__ theta_upper) {
    int idx = blockIdx.x * blockDim.x + threadIdx.x;
    if (idx >= PP * PP) return;
    int j = idx >> 10;          // / P
    int k = idx & (PP - 1);     // % P
    float v = 0.0f;
    if (k > j) {
        int t = j * PP - ((j * (j + 1)) >> 1) + (k - j - 1);
        v = theta_upper[t];
    }
    g_W[idx] = v;
}

// ---------------------------------------------------------------------------
// Kernel 2: fused tile GEMM + row-dot epilogue.
// Block (bx, by): rows [bx*128, +128), output columns k in [by*64, +64).
// C[TM][TN] = X_tile @ W[:, k-tile]; partial_y_i = sum_k x_ik * (beta_k + C_ik)
// Written to g_ypart[by*N + i] (deterministic; no atomics).
// ---------------------------------------------------------------------------
__global__ __launch_bounds__(256, 2)
void fused_gemm_rowdot_kernel(const float* __restrict__ X,
                              const float* __restrict__ beta) {
    __shared__ float Xs[TJ][TM];   // transposed X tile (j-major)
    __shared__ float Ws[TJ][TN];   // W tile (j-major)

    const int t  = threadIdx.x;       // 0..255
    const int tx = t & 15;            // col group 0..15  (4 cols each)
    const int ty = t >> 4;            // row group 0..15  (8 rows each)
    const int i0 = blockIdx.x * TM;
    const int k0 = blockIdx.y * TN;

    float acc[8][4];
#pragma unroll
    for (int ri = 0; ri < 8; ++ri)
#pragma unroll
        for (int ci = 0; ci < 4; ++ci) acc[ri][ci] = 0.0f;

    for (int j0 = 0; j0 < PP; j0 += TJ) {
        // --- load X tile [TM x TJ], store transposed into Xs[TJ][TM] ---
#pragma unroll
        for (int it = 0; it < 2; ++it) {
            int idx = t + it * 256;            // 0..511 float4 slots
            int r  = idx & 127;                // row within tile
            int cg = idx >> 7;                 // float4 column group 0..3
            float4 v = *(const float4*)&X[(size_t)(i0 + r) * PP + j0 + cg * 4];
            Xs[cg * 4 + 0][r] = v.x;
            Xs[cg * 4 + 1][r] = v.y;
            Xs[cg * 4 + 2][r] = v.z;
            Xs[cg * 4 + 3][r] = v.w;
        }
        // --- load W tile [TJ x TN] ---
        {
            int wr = t >> 4;                   // row 0..15
            int wc = t & 15;                   // float4 col 0..15
            *(float4*)&Ws[wr][wc * 4] =
                *(const float4*)&g_W[(size_t)(j0 + wr) * PP + k0 + wc * 4];
        }
        __syncthreads();

#pragma unroll
        for (int jj = 0; jj < TJ; ++jj) {
            float4 a0 = *(const float4*)&Xs[jj][ty * 8];
            float4 a1 = *(const float4*)&Xs[jj][ty * 8 + 4];
            float4 b  = *(const float4*)&Ws[jj][tx * 4];
            float a[8] = {a0.x, a0.y, a0.z, a0.w, a1.x, a1.y, a1.z, a1.w};
            float bb[4] = {b.x, b.y, b.z, b.w};
#pragma unroll
            for (int ri = 0; ri < 8; ++ri)
#pragma unroll
                for (int ci = 0; ci < 4; ++ci)
                    acc[ri][ci] = fmaf(a[ri], bb[ci], acc[ri][ci]);
        }
        __syncthreads();
    }

    // --- epilogue: part_i = sum_{ci} (acc + beta_k) * x_ik, reduce over tx ---
    float4 bq = *(const float4*)&beta[k0 + tx * 4];
    float bb[4] = {bq.x, bq.y, bq.z, bq.w};
    float part[8];
#pragma unroll
    for (int ri = 0; ri < 8; ++ri) {
        float4 xv = *(const float4*)&X[(size_t)(i0 + ty * 8 + ri) * PP + k0 + tx * 4];
        float s = (acc[ri][0] + bb[0]) * xv.x;
        s = fmaf(acc[ri][1] + bb[1], xv.y, s);
        s = fmaf(acc[ri][2] + bb[2], xv.z, s);
        s = fmaf(acc[ri][3] + bb[3], xv.w, s);
        part[ri] = s;
    }
    // butterfly over the 16 tx lanes (low 4 bits of lane id)
#pragma unroll
    for (int off = 8; off > 0; off >>= 1)
#pragma unroll
        for (int ri = 0; ri < 8; ++ri)
            part[ri] += __shfl_xor_sync(0xffffffffu, part[ri], off);

    if (tx == 0) {
#pragma unroll
        for (int ri = 0; ri < 8; ++ri)
            g_ypart[(size_t)blockIdx.y * NN + i0 + ty * 8 + ri] = part[ri];
    }
}

// ---------------------------------------------------------------------------
// Kernel 3: y[i] = beta0 + sum over k-tiles of partials
// ---------------------------------------------------------------------------
__global__ void reduce_kernel(const float* __restrict__ beta0, float* __restrict__ y) {
    int i = blockIdx.x * blockDim.x + threadIdx.x;
    if (i >= NN) return;
    float s = beta0[0];
#pragma unroll
    for (int g = 0; g < NKT; ++g) s += g_ypart[g * NN + i];
    y[i] = s;
}

extern "C" void kernel_launch(void* const* d_in, const int* in_sizes, int n_in,
                              void* d_out, int out_size) {
    const float* X     = (const float*)d_in[0];
    const float* beta0 = (const float*)d_in[1];
    const float* beta  = (const float*)d_in[2];
    const float* theta = (const float*)d_in[3];
    float* y = (float*)d_out;

    scatter_theta_kernel<<<(PP * PP + 255) / 256, 256>>>(theta);

    dim3 grid(NN / TM, PP / TN);   // (128, 16)
    fused_gemm_rowdot_kernel<<<grid, 256>>>(X, beta);

    reduce_kernel<<<(NN + 255) / 256, 256>>>(beta0, y);
}

// round 4
// speedup vs baseline: 3.4325x; 3.4325x over previous
#include <cuda_runtime.h>
#include <cuda_bf16.h>
#include <cstdint>

#define PP 1024
#define NROW 16384
#define TILE_M 128
#define TILE_N 128
#define KC 64
#define NCH (PP / KC)          // 16 k-chunks
#define NSLOT 32               // 8 col-blocks * 4 n-warps

// smem stage layout (bytes)
#define AHI 0
#define ALO 16384
#define BHI 32768
#define BLO 49152
#define STAGE_BYTES 65536
#define SMEM_TOTAL (2 * STAGE_BYTES)   // 128 KB

// Scratch (static __device__ — no allocation allowed)
__device__ __align__(16) __nv_bfloat16 g_Xhi[(size_t)NROW * PP];
__device__ __align__(16) __nv_bfloat16 g_Xlo[(size_t)NROW * PP];
__device__ __align__(16) __nv_bfloat16 g_Whi[(size_t)PP * PP];   // W^T layout: [n][k]
__device__ __align__(16) __nv_bfloat16 g_Wlo[(size_t)PP * PP];
__device__ float g_ypart[(size_t)NSLOT * NROW];

// ---------------- helpers ----------------
__device__ __forceinline__ uint32_t smem_u32(const void* p) {
    uint32_t a;
    asm("{ .reg .u64 t; cvta.to.shared.u64 t, %1; cvt.u32.u64 %0, t; }" : "=r"(a) : "l"(p));
    return a;
}
// 128B rows of bf16 (64 elems). 16B chunk swizzle: chunk ^= (row & 7)
__device__ __forceinline__ uint32_t sw(int row, int ch) {
    return (uint32_t)(row * 128 + ((ch ^ (row & 7)) << 4));
}
__device__ __forceinline__ void cp16(uint32_t dst, const void* src) {
    asm volatile("cp.async.cg.shared.global [%0], [%1], 16;" :: "r"(dst), "l"(src) : "memory");
}
__device__ __forceinline__ void ldmx4(uint32_t* r, uint32_t addr) {
    asm volatile("ldmatrix.sync.aligned.m8n8.x4.shared.b16 {%0,%1,%2,%3}, [%4];"
                 : "=r"(r[0]), "=r"(r[1]), "=r"(r[2]), "=r"(r[3]) : "r"(addr));
}
__device__ __forceinline__ void mma16816(float* c, const uint32_t* a, const uint32_t* b) {
    asm volatile(
        "mma.sync.aligned.m16n8k16.row.col.f32.bf16.bf16.f32 "
        "{%0,%1,%2,%3}, {%4,%5,%6,%7}, {%8,%9}, {%0,%1,%2,%3};"
        : "+f"(c[0]), "+f"(c[1]), "+f"(c[2]), "+f"(c[3])
        : "r"(a[0]), "r"(a[1]), "r"(a[2]), "r"(a[3]), "r"(b[0]), "r"(b[1]));
}

// ---------------------------------------------------------------------------
// Prep 1: split X into bf16 hi/lo
// ---------------------------------------------------------------------------
__global__ void split_X_kernel(const float* __restrict__ X) {
    size_t idx = (size_t)blockIdx.x * blockDim.x + threadIdx.x;   // over N*P/4
    float4 v = reinterpret_cast<const float4*>(X)[idx];
    float f[4] = {v.x, v.y, v.z, v.w};
    uint32_t hi[2], lo[2];
#pragma unroll
    for (int q = 0; q < 2; ++q) {
        __nv_bfloat16 h0 = __float2bfloat16(f[2 * q]);
        __nv_bfloat16 h1 = __float2bfloat16(f[2 * q + 1]);
        __nv_bfloat16 l0 = __float2bfloat16(f[2 * q] - __bfloat162float(h0));
        __nv_bfloat16 l1 = __float2bfloat16(f[2 * q + 1] - __bfloat162float(h1));
        hi[q] = (uint32_t)__bfloat16_as_ushort(h0) | ((uint32_t)__bfloat16_as_ushort(h1) << 16);
        lo[q] = (uint32_t)__bfloat16_as_ushort(l0) | ((uint32_t)__bfloat16_as_ushort(l1) << 16);
    }
    reinterpret_cast<uint2*>(g_Xhi)[idx] = make_uint2(hi[0], hi[1]);
    reinterpret_cast<uint2*>(g_Xlo)[idx] = make_uint2(lo[0], lo[1]);
}

// ---------------------------------------------------------------------------
// Prep 2: scatter theta into W^T [n][k] (nonzero for n>k), split bf16 hi/lo
// ---------------------------------------------------------------------------
__global__ void build_W_kernel(const float* __restrict__ theta) {
    int idx = blockIdx.x * blockDim.x + threadIdx.x;    // over P*P
    int n = idx >> 10, k = idx & (PP - 1);
    float v = 0.0f;
    if (n > k) v = theta[k * PP - ((k * (k + 1)) >> 1) + (n - k - 1)];
    __nv_bfloat16 h = __float2bfloat16(v);
    __nv_bfloat16 l = __float2bfloat16(v - __bfloat162float(h));
    g_Whi[idx] = h;
    g_Wlo[idx] = l;
}

// ---------------------------------------------------------------------------
// Main: bf16x3 mma.sync GEMM (128x128 tile) + fused (C+beta)·x rowdot epilogue
// ---------------------------------------------------------------------------
__global__ __launch_bounds__(256, 1)
void gemm_rowdot_mma(const float* __restrict__ X, const float* __restrict__ beta) {
    extern __shared__ char smem[];
    const uint32_t sbase = smem_u32(smem);
    const int tid = threadIdx.x;
    const int l = tid & 31;
    const int wid = tid >> 5;
    const int wm = wid & 1;        // 2 m-warps
    const int wn = wid >> 1;       // 4 n-warps
    const int m_base = wm * 64;
    const int n_base = wn * 32;
    const int i0 = blockIdx.x * TILE_M;
    const int n0 = blockIdx.y * TILE_N;

    float acc[4][4][4];            // [mi][ni][frag]
#pragma unroll
    for (int mi = 0; mi < 4; ++mi)
#pragma unroll
        for (int ni = 0; ni < 4; ++ni)
#pragma unroll
            for (int q = 0; q < 4; ++q) acc[mi][ni][q] = 0.0f;

    // --- async load of one stage: 4 tiles x 1024 chunks of 16B ---
    auto load_stage = [&](int c) {
        const uint32_t stg = sbase + (uint32_t)(c & 1) * STAGE_BYTES;
        const int k0 = c * KC;
#pragma unroll
        for (int it = 0; it < 4; ++it) {
            int u = tid + it * 256;
            int row = u >> 3, ch = u & 7;
            uint32_t d = sw(row, ch);
            size_t asrc = (size_t)(i0 + row) * PP + k0 + ch * 8;
            size_t bsrc = (size_t)(n0 + row) * PP + k0 + ch * 8;
            cp16(stg + AHI + d, g_Xhi + asrc);
            cp16(stg + ALO + d, g_Xlo + asrc);
            cp16(stg + BHI + d, g_Whi + bsrc);
            cp16(stg + BLO + d, g_Wlo + bsrc);
        }
        asm volatile("cp.async.commit_group;" ::: "memory");
    };

    load_stage(0);

    for (int c = 0; c < NCH; ++c) {
        if (c + 1 < NCH) {
            load_stage(c + 1);
            asm volatile("cp.async.wait_group 1;" ::: "memory");
        } else {
            asm volatile("cp.async.wait_group 0;" ::: "memory");
        }
        __syncthreads();

        const uint32_t stg = sbase + (uint32_t)(c & 1) * STAGE_BYTES;
#pragma unroll
        for (int ks = 0; ks < 4; ++ks) {
            uint32_t ahi[4][4], alo[4][4], bhi[4][2], blo[4][2];
            // A fragments: lanes 0-15 rows r, k-lo; lanes 16-31 rows r, k-hi
            {
                int r = l & 15, kh = l >> 4;
                int ch = ks * 2 + kh;
#pragma unroll
                for (int mi = 0; mi < 4; ++mi) {
                    uint32_t ad = sw(m_base + mi * 16 + r, ch);
                    ldmx4(ahi[mi], stg + AHI + ad);
                    ldmx4(alo[mi], stg + ALO + ad);
                }
            }
            // B fragments: 2 x ldmatrix.x4, each covers 2 n8-tiles x full k16
            {
                int nr_off = ((l >> 4) << 3) + (l & 7);
                int ch = ks * 2 + ((l >> 3) & 1);
#pragma unroll
                for (int np = 0; np < 2; ++np) {
                    uint32_t bd = sw(n_base + np * 16 + nr_off, ch);
                    uint32_t r4[4];
                    ldmx4(r4, stg + BHI + bd);
                    bhi[np * 2][0] = r4[0]; bhi[np * 2][1] = r4[1];
                    bhi[np * 2 + 1][0] = r4[2]; bhi[np * 2 + 1][1] = r4[3];
                    ldmx4(r4, stg + BLO + bd);
                    blo[np * 2][0] = r4[0]; blo[np * 2][1] = r4[1];
                    blo[np * 2 + 1][0] = r4[2]; blo[np * 2 + 1][1] = r4[3];
                }
            }
#pragma unroll
            for (int mi = 0; mi < 4; ++mi)
#pragma unroll
                for (int ni = 0; ni < 4; ++ni) {
                    mma16816(acc[mi][ni], ahi[mi], bhi[ni]);
                    mma16816(acc[mi][ni], ahi[mi], blo[ni]);
                    mma16816(acc[mi][ni], alo[mi], bhi[ni]);
                }
        }
        __syncthreads();
    }

    // --- fused epilogue: part_r = sum_c (C[r][c] + beta[c]) * X[r][c] ---
#pragma unroll
    for (int mi = 0; mi < 4; ++mi) {
        int r0 = i0 + m_base + mi * 16 + (l >> 2);
        int r1 = r0 + 8;
        float p0 = 0.0f, p1 = 0.0f;
#pragma unroll
        for (int ni = 0; ni < 4; ++ni) {
            int cc = n0 + n_base + ni * 8 + (l & 3) * 2;
            float2 bv  = *(const float2*)&beta[cc];
            float2 x0  = *(const float2*)&X[(size_t)r0 * PP + cc];
            float2 x1  = *(const float2*)&X[(size_t)r1 * PP + cc];
            p0 = fmaf(acc[mi][ni][0] + bv.x, x0.x, p0);
            p0 = fmaf(acc[mi][ni][1] + bv.y, x0.y, p0);
            p1 = fmaf(acc[mi][ni][2] + bv.x, x1.x, p1);
            p1 = fmaf(acc[mi][ni][3] + bv.y, x1.y, p1);
        }
        // reduce over the 4 lanes sharing a row (low 2 lane bits)
        p0 += __shfl_xor_sync(0xffffffffu, p0, 1);
        p0 += __shfl_xor_sync(0xffffffffu, p0, 2);
        p1 += __shfl_xor_sync(0xffffffffu, p1, 1);
        p1 += __shfl_xor_sync(0xffffffffu, p1, 2);
        if ((l & 3) == 0) {
            int slot = blockIdx.y * 4 + wn;
            g_ypart[(size_t)slot * NROW + r0] = p0;
            g_ypart[(size_t)slot * NROW + r1] = p1;
        }
    }
}

// ---------------------------------------------------------------------------
// Final: y[i] = beta0 + sum of 32 partials
// ---------------------------------------------------------------------------
__global__ void reduce_kernel(const float* __restrict__ beta0, float* __restrict__ y) {
    int i = blockIdx.x * blockDim.x + threadIdx.x;
    if (i >= NROW) return;
    float s = beta0[0];
#pragma unroll
    for (int g = 0; g < NSLOT; ++g) s += g_ypart[(size_t)g * NROW + i];
    y[i] = s;
}

extern "C" void kernel_launch(void* const* d_in, const int* in_sizes, int n_in,
                              void* d_out, int out_size) {
    const float* X     = (const float*)d_in[0];
    const float* beta0 = (const float*)d_in[1];
    const float* beta  = (const float*)d_in[2];
    const float* theta = (const float*)d_in[3];
    float* y = (float*)d_out;

    cudaFuncSetAttribute(gemm_rowdot_mma, cudaFuncAttributeMaxDynamicSharedMemorySize, SMEM_TOTAL);

    split_X_kernel<<<(NROW * PP / 4 + 255) / 256, 256>>>(X);
    build_W_kernel<<<(PP * PP + 255) / 256, 256>>>(theta);

    dim3 grid(NROW / TILE_M, PP / TILE_N);   // (128, 8)
    gemm_rowdot_mma<<<grid, 256, SMEM_TOTAL>>>(X, beta);

    reduce_kernel<<<(NROW + 255) / 256, 256>>>(beta0, y);
}

// round 6
// speedup vs baseline: 5.0126x; 1.4603x over previous
#include <cuda_runtime.h>
#include <cuda_bf16.h>
#include <cstdint>

#define PP 1024
#define NROW 16384
#define TILE_M 128
#define TILE_N 128
#define KC 64
#define NCH (PP / KC)          // 16 k-chunks
#define NSLOT 32               // 8 col-blocks * 4 n-warps

// smem stage layout (bytes)
#define AHI 0
#define ALO 16384
#define BHI 32768
#define BLO 49152
#define STAGE_BYTES 65536
#define SMEM_TOTAL (2 * STAGE_BYTES)   // 128 KB

// Scratch (static __device__ — no allocation allowed)
__device__ __align__(16) __nv_bfloat16 g_Xhi[(size_t)NROW * PP];
__device__ __align__(16) __nv_bfloat16 g_Xlo[(size_t)NROW * PP];
__device__ __align__(16) __nv_bfloat16 g_Whi[(size_t)PP * PP];   // W^T layout: [n][k]
__device__ __align__(16) __nv_bfloat16 g_Wlo[(size_t)PP * PP];
__device__ float g_ypart[(size_t)NSLOT * NROW];

// ---------------- helpers ----------------
__device__ __forceinline__ uint32_t smem_u32(const void* p) {
    uint32_t a;
    asm("{ .reg .u64 t; cvta.to.shared.u64 t, %1; cvt.u32.u64 %0, t; }" : "=r"(a) : "l"(p));
    return a;
}
// 128B rows of bf16 (64 elems). 16B chunk swizzle: chunk ^= (row & 7)
__device__ __forceinline__ uint32_t sw(int row, int ch) {
    return (uint32_t)(row * 128 + ((ch ^ (row & 7)) << 4));
}
__device__ __forceinline__ void cp16(uint32_t dst, const void* src) {
    asm volatile("cp.async.cg.shared.global [%0], [%1], 16;" :: "r"(dst), "l"(src) : "memory");
}
__device__ __forceinline__ void ldmx4(uint32_t* r, uint32_t addr) {
    asm volatile("ldmatrix.sync.aligned.m8n8.x4.shared.b16 {%0,%1,%2,%3}, [%4];"
                 : "=r"(r[0]), "=r"(r[1]), "=r"(r[2]), "=r"(r[3]) : "r"(addr));
}
__device__ __forceinline__ void mma16816(float* c, const uint32_t* a, const uint32_t* b) {
    asm volatile(
        "mma.sync.aligned.m16n8k16.row.col.f32.bf16.bf16.f32 "
        "{%0,%1,%2,%3}, {%4,%5,%6,%7}, {%8,%9}, {%0,%1,%2,%3};"
        : "+f"(c[0]), "+f"(c[1]), "+f"(c[2]), "+f"(c[3])
        : "r"(a[0]), "r"(a[1]), "r"(a[2]), "r"(a[3]), "r"(b[0]), "r"(b[1]));
}

// ---------------------------------------------------------------------------
// Prep 1: split X into bf16 hi/lo
// ---------------------------------------------------------------------------
__global__ void split_X_kernel(const float* __restrict__ X) {
    size_t idx = (size_t)blockIdx.x * blockDim.x + threadIdx.x;   // over N*P/4
    float4 v = reinterpret_cast<const float4*>(X)[idx];
    float f[4] = {v.x, v.y, v.z, v.w};
    uint32_t hi[2], lo[2];
#pragma unroll
    for (int q = 0; q < 2; ++q) {
        __nv_bfloat16 h0 = __float2bfloat16(f[2 * q]);
        __nv_bfloat16 h1 = __float2bfloat16(f[2 * q + 1]);
        __nv_bfloat16 l0 = __float2bfloat16(f[2 * q] - __bfloat162float(h0));
        __nv_bfloat16 l1 = __float2bfloat16(f[2 * q + 1] - __bfloat162float(h1));
        hi[q] = (uint32_t)__bfloat16_as_ushort(h0) | ((uint32_t)__bfloat16_as_ushort(h1) << 16);
        lo[q] = (uint32_t)__bfloat16_as_ushort(l0) | ((uint32_t)__bfloat16_as_ushort(l1) << 16);
    }
    reinterpret_cast<uint2*>(g_Xhi)[idx] = make_uint2(hi[0], hi[1]);
    reinterpret_cast<uint2*>(g_Xlo)[idx] = make_uint2(lo[0], lo[1]);
}

// ---------------------------------------------------------------------------
// Prep 2: scatter theta into W^T [n][k] (nonzero for n>k), split bf16 hi/lo
// ---------------------------------------------------------------------------
__global__ void build_W_kernel(const float* __restrict__ theta) {
    int idx = blockIdx.x * blockDim.x + threadIdx.x;    // over P*P
    int n = idx >> 10, k = idx & (PP - 1);
    float v = 0.0f;
    if (n > k) v = theta[k * PP - ((k * (k + 1)) >> 1) + (n - k - 1)];
    __nv_bfloat16 h = __float2bfloat16(v);
    __nv_bfloat16 l = __float2bfloat16(v - __bfloat162float(h));
    g_Whi[idx] = h;
    g_Wlo[idx] = l;
}

// ---------------------------------------------------------------------------
// Main: bf16x3 mma.sync GEMM (128x128 tile) + fused (C+beta)·x rowdot epilogue.
// Triangular skip: W^T[n][k] == 0 for k >= n, so the CTA at n-tile bn only
// needs k-chunks with k0 < n0+128  =>  nch_eff = 2*(bn+1).
// ---------------------------------------------------------------------------
__global__ __launch_bounds__(256, 1)
void gemm_rowdot_mma(const float* __restrict__ X, const float* __restrict__ beta) {
    extern __shared__ char smem[];
    const uint32_t sbase = smem_u32(smem);
    const int tid = threadIdx.x;
    const int l = tid & 31;
    const int wid = tid >> 5;
    const int wm = wid & 1;        // 2 m-warps
    const int wn = wid >> 1;       // 4 n-warps
    const int m_base = wm * 64;
    const int n_base = wn * 32;
    const int i0 = blockIdx.x * TILE_M;
    const int n0 = blockIdx.y * TILE_N;
    const int nch_eff = 2 * (blockIdx.y + 1);   // <= NCH

    float acc[4][4][4];            // [mi][ni][frag]
#pragma unroll
    for (int mi = 0; mi < 4; ++mi)
#pragma unroll
        for (int ni = 0; ni < 4; ++ni)
#pragma unroll
            for (int q = 0; q < 4; ++q) acc[mi][ni][q] = 0.0f;

    // --- async load of one stage: 4 tiles x 1024 chunks of 16B ---
    auto load_stage = [&](int c) {
        const uint32_t stg = sbase + (uint32_t)(c & 1) * STAGE_BYTES;
        const int k0 = c * KC;
#pragma unroll
        for (int it = 0; it < 4; ++it) {
            int u = tid + it * 256;
            int row = u >> 3, ch = u & 7;
            uint32_t d = sw(row, ch);
            size_t asrc = (size_t)(i0 + row) * PP + k0 + ch * 8;
            size_t bsrc = (size_t)(n0 + row) * PP + k0 + ch * 8;
            cp16(stg + AHI + d, g_Xhi + asrc);
            cp16(stg + ALO + d, g_Xlo + asrc);
            cp16(stg + BHI + d, g_Whi + bsrc);
            cp16(stg + BLO + d, g_Wlo + bsrc);
        }
        asm volatile("cp.async.commit_group;" ::: "memory");
    };

    load_stage(0);

    for (int c = 0; c < nch_eff; ++c) {
        if (c + 1 < nch_eff) {
            load_stage(c + 1);
            asm volatile("cp.async.wait_group 1;" ::: "memory");
        } else {
            asm volatile("cp.async.wait_group 0;" ::: "memory");
        }
        __syncthreads();

        const uint32_t stg = sbase + (uint32_t)(c & 1) * STAGE_BYTES;
#pragma unroll
        for (int ks = 0; ks < 4; ++ks) {
            uint32_t ahi[4][4], alo[4][4], bhi[4][2], blo[4][2];
            // A fragments: lanes 0-15 rows r, k-lo; lanes 16-31 rows r, k-hi
            {
                int r = l & 15, kh = l >> 4;
                int ch = ks * 2 + kh;
#pragma unroll
                for (int mi = 0; mi < 4; ++mi) {
                    uint32_t ad = sw(m_base + mi * 16 + r, ch);
                    ldmx4(ahi[mi], stg + AHI + ad);
                    ldmx4(alo[mi], stg + ALO + ad);
                }
            }
            // B fragments: 2 x ldmatrix.x4, each covers 2 n8-tiles x full k16
            {
                int nr_off = ((l >> 4) << 3) + (l & 7);
                int ch = ks * 2 + ((l >> 3) & 1);
#pragma unroll
                for (int np = 0; np < 2; ++np) {
                    uint32_t bd = sw(n_base + np * 16 + nr_off, ch);
                    uint32_t r4[4];
                    ldmx4(r4, stg + BHI + bd);
                    bhi[np * 2][0] = r4[0]; bhi[np * 2][1] = r4[1];
                    bhi[np * 2 + 1][0] = r4[2]; bhi[np * 2 + 1][1] = r4[3];
                    ldmx4(r4, stg + BLO + bd);
                    blo[np * 2][0] = r4[0]; blo[np * 2][1] = r4[1];
                    blo[np * 2 + 1][0] = r4[2]; blo[np * 2 + 1][1] = r4[3];
                }
            }
#pragma unroll
            for (int mi = 0; mi < 4; ++mi)
#pragma unroll
                for (int ni = 0; ni < 4; ++ni) {
                    mma16816(acc[mi][ni], ahi[mi], bhi[ni]);
                    mma16816(acc[mi][ni], ahi[mi], blo[ni]);
                    mma16816(acc[mi][ni], alo[mi], bhi[ni]);
                }
        }
        __syncthreads();
    }

    // --- fused epilogue: part_r = sum_c (C[r][c] + beta[c]) * X[r][c] ---
#pragma unroll
    for (int mi = 0; mi < 4; ++mi) {
        int r0 = i0 + m_base + mi * 16 + (l >> 2);
        int r1 = r0 + 8;
        float p0 = 0.0f, p1 = 0.0f;
#pragma unroll
        for (int ni = 0; ni < 4; ++ni) {
            int cc = n0 + n_base + ni * 8 + (l & 3) * 2;
            float2 bv  = *(const float2*)&beta[cc];
            float2 x0  = *(const float2*)&X[(size_t)r0 * PP + cc];
            float2 x1  = *(const float2*)&X[(size_t)r1 * PP + cc];
            p0 = fmaf(acc[mi][ni][0] + bv.x, x0.x, p0);
            p0 = fmaf(acc[mi][ni][1] + bv.y, x0.y, p0);
            p1 = fmaf(acc[mi][ni][2] + bv.x, x1.x, p1);
            p1 = fmaf(acc[mi][ni][3] + bv.y, x1.y, p1);
        }
        // reduce over the 4 lanes sharing a row (low 2 lane bits)
        p0 += __shfl_xor_sync(0xffffffffu, p0, 1);
        p0 += __shfl_xor_sync(0xffffffffu, p0, 2);
        p1 += __shfl_xor_sync(0xffffffffu, p1, 1);
        p1 += __shfl_xor_sync(0xffffffffu, p1, 2);
        if ((l & 3) == 0) {
            int slot = blockIdx.y * 4 + wn;
            g_ypart[(size_t)slot * NROW + r0] = p0;
            g_ypart[(size_t)slot * NROW + r1] = p1;
        }
    }
}

// ---------------------------------------------------------------------------
// Final: y[i] = beta0 + sum of 32 partials
// ---------------------------------------------------------------------------
__global__ void reduce_kernel(const float* __restrict__ beta0, float* __restrict__ y) {
    int i = blockIdx.x * blockDim.x + threadIdx.x;
    if (i >= NROW) return;
    float s = beta0[0];
#pragma unroll
    for (int g = 0; g < NSLOT; ++g) s += g_ypart[(size_t)g * NROW + i];
    y[i] = s;
}

extern "C" void kernel_launch(void* const* d_in, const int* in_sizes, int n_in,
                              void* d_out, int out_size) {
    const float* X     = (const float*)d_in[0];
    const float* beta0 = (const float*)d_in[1];
    const float* beta  = (const float*)d_in[2];
    const float* theta = (const float*)d_in[3];
    float* y = (float*)d_out;

    cudaFuncSetAttribute(gemm_rowdot_mma, cudaFuncAttributeMaxDynamicSharedMemorySize, SMEM_TOTAL);

    split_X_kernel<<<(NROW * PP / 4 + 255) / 256, 256>>>(X);
    build_W_kernel<<<(PP * PP + 255) / 256, 256>>>(theta);

    dim3 grid(NROW / TILE_M, PP / TILE_N);   // (128, 8)
    gemm_rowdot_mma<<<grid, 256, SMEM_TOTAL>>>(X, beta);

    reduce_kernel<<<(NROW + 255) / 256, 256>>>(beta0, y);
}

// round 7
// speedup vs baseline: 5.3104x; 1.0594x over previous
#include <cuda_runtime.h>
#include <cuda_bf16.h>
#include <cstdint>

#define PP 1024
#define NROW 16384
#define TILE_M 128
#define TILE_N 128
#define KC 64
#define NCH (PP / KC)          // 16 k-chunks
#define NSLOT 32               // 8 col-blocks * 4 n-warps

// smem stage layout (bytes)
#define AHI 0
#define ALO 16384
#define BHI 32768
#define BLO 49152
#define STAGE_BYTES 65536
#define SMEM_TOTAL (2 * STAGE_BYTES)   // 128 KB

// Scratch (static __device__ — no allocation allowed)
__device__ __align__(16) __nv_bfloat16 g_Xhi[(size_t)NROW * PP];
__device__ __align__(16) __nv_bfloat16 g_Xlo[(size_t)NROW * PP];
__device__ __align__(16) __nv_bfloat16 g_Whi[(size_t)PP * PP];   // W^T layout: [n][k]
__device__ __align__(16) __nv_bfloat16 g_Wlo[(size_t)PP * PP];
__device__ float g_ypart[(size_t)NSLOT * NROW];

// ---------------- helpers ----------------
__device__ __forceinline__ uint32_t smem_u32(const void* p) {
    uint32_t a;
    asm("{ .reg .u64 t; cvta.to.shared.u64 t, %1; cvt.u32.u64 %0, t; }" : "=r"(a) : "l"(p));
    return a;
}
// 128B rows of bf16 (64 elems). 16B chunk swizzle: chunk ^= (row & 7)
__device__ __forceinline__ uint32_t sw(int row, int ch) {
    return (uint32_t)(row * 128 + ((ch ^ (row & 7)) << 4));
}
__device__ __forceinline__ void cp16(uint32_t dst, const void* src) {
    asm volatile("cp.async.cg.shared.global [%0], [%1], 16;" :: "r"(dst), "l"(src) : "memory");
}
__device__ __forceinline__ void ldmx4(uint32_t* r, uint32_t addr) {
    asm volatile("ldmatrix.sync.aligned.m8n8.x4.shared.b16 {%0,%1,%2,%3}, [%4];"
                 : "=r"(r[0]), "=r"(r[1]), "=r"(r[2]), "=r"(r[3]) : "r"(addr));
}
__device__ __forceinline__ void mma16816(float* c, const uint32_t* a, const uint32_t* b) {
    asm volatile(
        "mma.sync.aligned.m16n8k16.row.col.f32.bf16.bf16.f32 "
        "{%0,%1,%2,%3}, {%4,%5,%6,%7}, {%8,%9}, {%0,%1,%2,%3};"
        : "+f"(c[0]), "+f"(c[1]), "+f"(c[2]), "+f"(c[3])
        : "r"(a[0]), "r"(a[1]), "r"(a[2]), "r"(a[3]), "r"(b[0]), "r"(b[1]));
}

// ---------------------------------------------------------------------------
// Prep 1: split X into bf16 hi/lo
// ---------------------------------------------------------------------------
__global__ void split_X_kernel(const float* __restrict__ X) {
    size_t idx = (size_t)blockIdx.x * blockDim.x + threadIdx.x;   // over N*P/4
    float4 v = reinterpret_cast<const float4*>(X)[idx];
    float f[4] = {v.x, v.y, v.z, v.w};
    uint32_t hi[2], lo[2];
#pragma unroll
    for (int q = 0; q < 2; ++q) {
        __nv_bfloat16 h0 = __float2bfloat16(f[2 * q]);
        __nv_bfloat16 h1 = __float2bfloat16(f[2 * q + 1]);
        __nv_bfloat16 l0 = __float2bfloat16(f[2 * q] - __bfloat162float(h0));
        __nv_bfloat16 l1 = __float2bfloat16(f[2 * q + 1] - __bfloat162float(h1));
        hi[q] = (uint32_t)__bfloat16_as_ushort(h0) | ((uint32_t)__bfloat16_as_ushort(h1) << 16);
        lo[q] = (uint32_t)__bfloat16_as_ushort(l0) | ((uint32_t)__bfloat16_as_ushort(l1) << 16);
    }
    reinterpret_cast<uint2*>(g_Xhi)[idx] = make_uint2(hi[0], hi[1]);
    reinterpret_cast<uint2*>(g_Xlo)[idx] = make_uint2(lo[0], lo[1]);
}

// ---------------------------------------------------------------------------
// Prep 2: scatter theta into W^T [n][k] (nonzero for n>k), split bf16 hi/lo
// ---------------------------------------------------------------------------
__global__ void build_W_kernel(const float* __restrict__ theta) {
    int idx = blockIdx.x * blockDim.x + threadIdx.x;    // over P*P
    int n = idx >> 10, k = idx & (PP - 1);
    float v = 0.0f;
    if (n > k) v = theta[k * PP - ((k * (k + 1)) >> 1) + (n - k - 1)];
    __nv_bfloat16 h = __float2bfloat16(v);
    __nv_bfloat16 l = __float2bfloat16(v - __bfloat162float(h));
    g_Whi[idx] = h;
    g_Wlo[idx] = l;
}

// ---------------------------------------------------------------------------
// Main: bf16x3 mma.sync GEMM (128x128 tile) + fused (C+beta)·x rowdot epilogue.
// Triangular skip: W^T[n][k] == 0 for k >= n  =>  nch_eff = 2*(bn+1).
// LPT scheduling: 1D grid, heavy n-tiles (large bn) launch first so the wave
// scheduler backfills with light CTAs (greedy longest-processing-time).
// ---------------------------------------------------------------------------
__global__ __launch_bounds__(256, 1)
void gemm_rowdot_mma(const float* __restrict__ X, const float* __restrict__ beta) {
    extern __shared__ char smem[];
    const uint32_t sbase = smem_u32(smem);
    const int tid = threadIdx.x;
    const int l = tid & 31;
    const int wid = tid >> 5;
    const int wm = wid & 1;        // 2 m-warps
    const int wn = wid >> 1;       // 4 n-warps
    const int m_base = wm * 64;
    const int n_base = wn * 32;

    // heavy-first decode: first 128 CTAs take bn=7, next 128 bn=6, ...
    const int bn = 7 - (int)(blockIdx.x >> 7);
    const int bx = (int)(blockIdx.x & 127);
    const int i0 = bx * TILE_M;
    const int n0 = bn * TILE_N;
    const int nch_eff = 2 * (bn + 1);   // <= NCH

    float acc[4][4][4];            // [mi][ni][frag]
#pragma unroll
    for (int mi = 0; mi < 4; ++mi)
#pragma unroll
        for (int ni = 0; ni < 4; ++ni)
#pragma unroll
            for (int q = 0; q < 4; ++q) acc[mi][ni][q] = 0.0f;

    // --- async load of one stage: 4 tiles x 1024 chunks of 16B ---
    auto load_stage = [&](int c) {
        const uint32_t stg = sbase + (uint32_t)(c & 1) * STAGE_BYTES;
        const int k0 = c * KC;
#pragma unroll
        for (int it = 0; it < 4; ++it) {
            int u = tid + it * 256;
            int row = u >> 3, ch = u & 7;
            uint32_t d = sw(row, ch);
            size_t asrc = (size_t)(i0 + row) * PP + k0 + ch * 8;
            size_t bsrc = (size_t)(n0 + row) * PP + k0 + ch * 8;
            cp16(stg + AHI + d, g_Xhi + asrc);
            cp16(stg + ALO + d, g_Xlo + asrc);
            cp16(stg + BHI + d, g_Whi + bsrc);
            cp16(stg + BLO + d, g_Wlo + bsrc);
        }
        asm volatile("cp.async.commit_group;" ::: "memory");
    };

    load_stage(0);

    for (int c = 0; c < nch_eff; ++c) {
        if (c + 1 < nch_eff) {
            load_stage(c + 1);
            asm volatile("cp.async.wait_group 1;" ::: "memory");
        } else {
            asm volatile("cp.async.wait_group 0;" ::: "memory");
        }
        __syncthreads();

        const uint32_t stg = sbase + (uint32_t)(c & 1) * STAGE_BYTES;
#pragma unroll
        for (int ks = 0; ks < 4; ++ks) {
            uint32_t ahi[4][4], alo[4][4], bhi[4][2], blo[4][2];
            // A fragments: lanes 0-15 rows r, k-lo; lanes 16-31 rows r, k-hi
            {
                int r = l & 15, kh = l >> 4;
                int ch = ks * 2 + kh;
#pragma unroll
                for (int mi = 0; mi < 4; ++mi) {
                    uint32_t ad = sw(m_base + mi * 16 + r, ch);
                    ldmx4(ahi[mi], stg + AHI + ad);
                    ldmx4(alo[mi], stg + ALO + ad);
                }
            }
            // B fragments: 2 x ldmatrix.x4, each covers 2 n8-tiles x full k16
            {
                int nr_off = ((l >> 4) << 3) + (l & 7);
                int ch = ks * 2 + ((l >> 3) & 1);
#pragma unroll
                for (int np = 0; np < 2; ++np) {
                    uint32_t bd = sw(n_base + np * 16 + nr_off, ch);
                    uint32_t r4[4];
                    ldmx4(r4, stg + BHI + bd);
                    bhi[np * 2][0] = r4[0]; bhi[np * 2][1] = r4[1];
                    bhi[np * 2 + 1][0] = r4[2]; bhi[np * 2 + 1][1] = r4[3];
                    ldmx4(r4, stg + BLO + bd);
                    blo[np * 2][0] = r4[0]; blo[np * 2][1] = r4[1];
                    blo[np * 2 + 1][0] = r4[2]; blo[np * 2 + 1][1] = r4[3];
                }
            }
#pragma unroll
            for (int mi = 0; mi < 4; ++mi)
#pragma unroll
                for (int ni = 0; ni < 4; ++ni) {
                    mma16816(acc[mi][ni], ahi[mi], bhi[ni]);
                    mma16816(acc[mi][ni], ahi[mi], blo[ni]);
                    mma16816(acc[mi][ni], alo[mi], bhi[ni]);
                }
        }
        __syncthreads();
    }

    // --- fused epilogue: part_r = sum_c (C[r][c] + beta[c]) * X[r][c] ---
#pragma unroll
    for (int mi = 0; mi < 4; ++mi) {
        int r0 = i0 + m_base + mi * 16 + (l >> 2);
        int r1 = r0 + 8;
        float p0 = 0.0f, p1 = 0.0f;
#pragma unroll
        for (int ni = 0; ni < 4; ++ni) {
            int cc = n0 + n_base + ni * 8 + (l & 3) * 2;
            float2 bv  = *(const float2*)&beta[cc];
            float2 x0  = *(const float2*)&X[(size_t)r0 * PP + cc];
            float2 x1  = *(const float2*)&X[(size_t)r1 * PP + cc];
            p0 = fmaf(acc[mi][ni][0] + bv.x, x0.x, p0);
            p0 = fmaf(acc[mi][ni][1] + bv.y, x0.y, p0);
            p1 = fmaf(acc[mi][ni][2] + bv.x, x1.x, p1);
            p1 = fmaf(acc[mi][ni][3] + bv.y, x1.y, p1);
        }
        // reduce over the 4 lanes sharing a row (low 2 lane bits)
        p0 += __shfl_xor_sync(0xffffffffu, p0, 1);
        p0 += __shfl_xor_sync(0xffffffffu, p0, 2);
        p1 += __shfl_xor_sync(0xffffffffu, p1, 1);
        p1 += __shfl_xor_sync(0xffffffffu, p1, 2);
        if ((l & 3) == 0) {
            int slot = bn * 4 + wn;
            g_ypart[(size_t)slot * NROW + r0] = p0;
            g_ypart[(size_t)slot * NROW + r1] = p1;
        }
    }
}

// ---------------------------------------------------------------------------
// Final: y[i] = beta0 + sum of 32 partials
// ---------------------------------------------------------------------------
__global__ void reduce_kernel(const float* __restrict__ beta0, float* __restrict__ y) {
    int i = blockIdx.x * blockDim.x + threadIdx.x;
    if (i >= NROW) return;
    float s = beta0[0];
#pragma unroll
    for (int g = 0; g < NSLOT; ++g) s += g_ypart[(size_t)g * NROW + i];
    y[i] = s;
}

extern "C" void kernel_launch(void* const* d_in, const int* in_sizes, int n_in,
                              void* d_out, int out_size) {
    const float* X     = (const float*)d_in[0];
    const float* beta0 = (const float*)d_in[1];
    const float* beta  = (const float*)d_in[2];
    const float* theta = (const float*)d_in[3];
    float* y = (float*)d_out;

    cudaFuncSetAttribute(gemm_rowdot_mma, cudaFuncAttributeMaxDynamicSharedMemorySize, SMEM_TOTAL);

    split_X_kernel<<<(NROW * PP / 4 + 255) / 256, 256>>>(X);
    build_W_kernel<<<(PP * PP + 255) / 256, 256>>>(theta);

    gemm_rowdot_mma<<<1024, 256, SMEM_TOTAL>>>(X, beta);

    reduce_kernel<<<(NROW + 255) / 256, 256>>>(beta0, y);
}